// round 7
// baseline (speedup 1.0000x reference)
#include <cuda_runtime.h>
#include <math.h>

#define BB 64
#define SS 512
#define HH 768
#define LL 9
#define NTOK (BB*SS)
#define TPW 4              // tokens per warp
#define WPB 8              // warps per block (256 threads)
#define TOKPB 32           // tokens per block (one row spans 16 blocks)
#define KC 128             // k-floats per pipeline stage
#define NST 4              // ring slots
#define NITER (HH/KC)      // 6 stages
#define STAGE_F (TOKPB*KC) // 4096 floats = 16KB per stage

typedef unsigned long long u64;

__device__ __forceinline__ u64 pack2(float lo, float hi) {
    u64 r; asm("mov.b64 %0, {%1, %2};" : "=l"(r) : "f"(lo), "f"(hi)); return r;
}
__device__ __forceinline__ void unpack2(u64 v, float &lo, float &hi) {
    asm("mov.b64 {%0, %1}, %2;" : "=f"(lo), "=f"(hi) : "l"(v));
}
__device__ __forceinline__ void ffma2(u64 &d, u64 a, u64 b) {
    asm("fma.rn.f32x2 %0, %1, %2, %0;" : "+l"(d) : "l"(a), "l"(b));
}
__device__ __forceinline__ void cp_async16(unsigned saddr, const void* gptr) {
    asm volatile("cp.async.cg.shared.global [%0], [%1], 16;" :: "r"(saddr), "l"(gptr));
}
__device__ __forceinline__ void cp_commit() {
    asm volatile("cp.async.commit_group;");
}
__device__ __forceinline__ void cp_wait2() {
    asm volatile("cp.async.wait_group 2;");
}

// ---------------------------------------------------------------------------
// Single fused kernel, cp.async-pipelined:
//   1. issue 3 stages of X into smem ring (48KB in flight at all times)
//   2. per-block re-scan of this row's valid_mask -> slot code per token
//   3. tall-skinny GEMM [4 tok/warp, 768] @ [768, 9]:
//      X from smem ring (LDS.128), W transposed in smem (LDS.128 -> two
//      f32x2 k-pair operands), f32x2 FMAs. One barrier per stage.
//   4. warp butterfly reduce + bias + softmax + compacting scatter
//      (invalid tokens write softmax(bias) to tail slots; bijection)
// ---------------------------------------------------------------------------
__global__ __launch_bounds__(256, 2) void bertner_kernel(
    const float* __restrict__ X, const int* __restrict__ mask,
    const float* __restrict__ W, const float* __restrict__ bias,
    float* __restrict__ out) {

    extern __shared__ float dyns[];
    float* sX   = dyns;                 // [NST][STAGE_F]  64KB ring
    float* shWT = dyns + NST * STAGE_F; // [LL][HH]        27.6KB transposed W
    __shared__ int sh_slot[TOKPB];
    __shared__ int sh_wsum[WPB];

    int tid  = threadIdx.x;
    int lane = tid & 31;
    int wid  = tid >> 5;

    int tokblk = blockIdx.x * TOKPB;
    int row    = tokblk >> 9;          // / SS
    int r0     = tokblk & (SS - 1);    // row-local index of first token

    const float* xg = X + (size_t)tokblk * HH;
    unsigned sX_u = (unsigned)__cvta_generic_to_shared(sX);

    // ---- prologue: issue stages 0..2 (3 groups in flight) ----
    #pragma unroll
    for (int s = 0; s < 3; s++) {
        #pragma unroll
        for (int w = 0; w < 4; w++) {
            int c   = w * 256 + tid;       // 0..1023 float4 chunks
            int tok = c >> 5;
            int off = c & 31;
            cp_async16(sX_u + (unsigned)((s * STAGE_F + tok * KC + off * 4) * 4),
                       xg + tok * HH + s * KC + off * 4);
        }
        cp_commit();
    }

    // ---- W transpose into smem (overlaps with in-flight cp.async) ----
    for (int k = tid; k < HH; k += 256) {
        #pragma unroll
        for (int j = 0; j < LL; j++) shWT[j * HH + k] = W[k * LL + j];
    }

    // ---- per-row compaction scan (block redundantly scans its whole row) ----
    int2 m2 = ((const int2*)(mask + row * SS))[tid];   // tokens 2*tid, 2*tid+1
    int msum = m2.x + m2.y;
    int v = msum;
    #pragma unroll
    for (int o = 1; o < 32; o <<= 1) {
        int n = __shfl_up_sync(0xffffffffu, v, o);
        if (lane >= o) v += n;
    }
    if (lane == 31) sh_wsum[wid] = v;
    __syncthreads();

    int wpre = 0, total = 0;
    #pragma unroll
    for (int w = 0; w < WPB; w++) {
        int s = sh_wsum[w];
        if (w < wid) wpre += s;
        total += s;
    }
    int run = wpre + v - msum;         // exclusive valid-prefix before token 2*tid

    int mm[2] = {m2.x, m2.y};
    #pragma unroll
    for (int c = 0; c < 2; c++) {
        int sc = 2 * tid + c;
        int code;
        if (mm[c]) { code = run; run++; }
        else       { code = ~(total + sc - run); }   // tail slot, encoded negative
        if (sc >= r0 && sc < r0 + TOKPB) sh_slot[sc - r0] = code;
    }

    // ---- main pipelined GEMM ----
    u64 acc[TPW][LL];
    #pragma unroll
    for (int t = 0; t < TPW; t++)
        #pragma unroll
        for (int j = 0; j < LL; j++) acc[t][j] = 0ull;

    for (int i = 0; i < NITER; i++) {
        cp_wait2();            // stage i resident (2 newer groups may be pending)
        __syncthreads();       // all threads see stage i; slot (i-1)&3 free to refill

        // refill ring ASAP (into the slot consumed at iter i-1)
        if (i + 3 < NITER) {
            int s  = i + 3;
            int sl = s & (NST - 1);
            #pragma unroll
            for (int w = 0; w < 4; w++) {
                int c   = w * 256 + tid;
                int tok = c >> 5;
                int off = c & 31;
                cp_async16(sX_u + (unsigned)((sl * STAGE_F + tok * KC + off * 4) * 4),
                           xg + tok * HH + s * KC + off * 4);
            }
        }
        cp_commit();           // empty group in tail iters keeps wait count uniform

        int slot = i & (NST - 1);
        const float* xs = sX + slot * STAGE_F + (wid * TPW) * KC + 4 * lane;
        const float* wk = shWT + i * KC + 4 * lane;

        float4 xv[TPW];
        #pragma unroll
        for (int t = 0; t < TPW; t++) xv[t] = *(const float4*)(xs + t * KC);

        u64 x01[TPW], x23[TPW];
        #pragma unroll
        for (int t = 0; t < TPW; t++) {
            x01[t] = pack2(xv[t].x, xv[t].y);
            x23[t] = pack2(xv[t].z, xv[t].w);
        }

        #pragma unroll
        for (int j = 0; j < LL; j++) {
            float4 wv = *(const float4*)(wk + j * HH);   // LDS.128, conflict-free
            u64 w01 = pack2(wv.x, wv.y);
            u64 w23 = pack2(wv.z, wv.w);
            #pragma unroll
            for (int t = 0; t < TPW; t++) {
                ffma2(acc[t][j], x01[t], w01);
                ffma2(acc[t][j], x23[t], w23);
            }
        }
    }

    // ---- fold k-pairs, then butterfly: every lane ends with full sums ----
    float r[TPW][LL];
    #pragma unroll
    for (int t = 0; t < TPW; t++)
        #pragma unroll
        for (int j = 0; j < LL; j++) {
            float lo, hi;
            unpack2(acc[t][j], lo, hi);
            r[t][j] = lo + hi;
        }
    #pragma unroll
    for (int t = 0; t < TPW; t++)
        #pragma unroll
        for (int j = 0; j < LL; j++)
            #pragma unroll
            for (int o = 16; o > 0; o >>= 1)
                r[t][j] += __shfl_xor_sync(0xffffffffu, r[t][j], o);

    // ---- bias + bias-softmax precompute (cheap, per thread) ----
    float bb[LL], be[LL];
    #pragma unroll
    for (int j = 0; j < LL; j++) bb[j] = bias[j];
    float bmx = bb[0];
    #pragma unroll
    for (int j = 1; j < LL; j++) bmx = fmaxf(bmx, bb[j]);
    float bsum = 0.f;
    #pragma unroll
    for (int j = 0; j < LL; j++) { be[j] = expf(bb[j] - bmx); bsum += be[j]; }
    float binv = 1.f / bsum;

    // ---- finalize: lanes 0..3 each own one token (static indexing) ----
    #pragma unroll
    for (int t = 0; t < TPW; t++) {
        if (lane == t) {
            int code = sh_slot[wid * TPW + t];
            if (code >= 0) {
                float v2[LL];
                float mx = -1e30f;
                #pragma unroll
                for (int j = 0; j < LL; j++) {
                    v2[j] = r[t][j] + bb[j];
                    mx = fmaxf(mx, v2[j]);
                }
                float ssum = 0.f;
                #pragma unroll
                for (int j = 0; j < LL; j++) { v2[j] = expf(v2[j] - mx); ssum += v2[j]; }
                float inv = 1.f / ssum;
                float* o = out + ((size_t)row * SS + code) * LL;
                #pragma unroll
                for (int j = 0; j < LL; j++) o[j] = v2[j] * inv;
            } else {
                int islot = ~code;
                float* o = out + ((size_t)row * SS + islot) * LL;
                #pragma unroll
                for (int j = 0; j < LL; j++) o[j] = be[j] * binv;
            }
        }
    }
}

// ---------------------------------------------------------------------------
// Launch. Inputs (metadata order): sequence_output f32[64*512*768],
// valid_mask i32[64*512], W f32[768*9], b f32[9]. Output f32[64*512*9].
// ---------------------------------------------------------------------------
extern "C" void kernel_launch(void* const* d_in, const int* in_sizes, int n_in,
                              void* d_out, int out_size) {
    const float* X    = (const float*)d_in[0];
    const int*   mask = (const int*)d_in[1];
    const float* W    = (const float*)d_in[2];
    const float* bias = (const float*)d_in[3];
    float* out = (float*)d_out;

    int smem = (NST * STAGE_F + LL * HH) * (int)sizeof(float);  // 93184 B
    cudaFuncSetAttribute(bertner_kernel,
                         cudaFuncAttributeMaxDynamicSharedMemorySize, smem);
    bertner_kernel<<<NTOK / TOKPB, 256, smem>>>(X, mask, W, bias, out);
}

// round 8
// speedup vs baseline: 1.4333x; 1.4333x over previous
#include <cuda_runtime.h>
#include <math.h>

#define BB 64
#define SS 512
#define HH 768
#define LL 9
#define NTOK (BB*SS)
#define TPW 4              // tokens per warp
#define WPB 8              // warps per block (256 threads)
#define TOKPB 32           // tokens per block (one row spans 16 blocks)
#define NLP 5              // label pairs (9 labels + 1 zero pad)
#define NITER 12           // 64-float k-chunks

typedef unsigned long long u64;

__device__ __forceinline__ u64 pack2(float lo, float hi) {
    u64 r; asm("mov.b64 %0, {%1, %2};" : "=l"(r) : "f"(lo), "f"(hi)); return r;
}
__device__ __forceinline__ u64 dup2(float v) {
    u64 r; asm("mov.b64 %0, {%1, %1};" : "=l"(r) : "f"(v)); return r;
}
__device__ __forceinline__ void unpack2(u64 v, float &lo, float &hi) {
    asm("mov.b64 {%0, %1}, %2;" : "=f"(lo), "=f"(hi) : "l"(v));
}
__device__ __forceinline__ void ffma2(u64 &d, u64 a, u64 b) {
    asm("fma.rn.f32x2 %0, %1, %2, %0;" : "+l"(d) : "l"(a), "l"(b));
}

// ---------------------------------------------------------------------------
// Single fused kernel, register-prefetch pipelined (distance 2):
//   1. prologue: issue X loads for k-chunks 0,1 (in flight during init)
//   2. W pre-packed into smem as f32x2 label-pairs, stride 5 u64 per k
//      (bank = 10*lane mod 32 -> conflict-free LDS.64)
//   3. per-block re-scan of this row's valid_mask -> slot code per token
//   4. 12-iter GEMM loop: at iter c, FIRST issue loads for chunk c+2 into a
//      rotating 3-slot register buffer, THEN compute chunk c. Each warp keeps
//      ~16 LDG.32 (2KB) outstanding continuously -> steady DRAM pull.
//   5. warp butterfly reduce + bias + softmax + compacting scatter
// ---------------------------------------------------------------------------
__global__ __launch_bounds__(256, 2) void bertner_kernel(
    const float* __restrict__ X, const int* __restrict__ mask,
    const float* __restrict__ W, const float* __restrict__ bias,
    float* __restrict__ out) {

    __shared__ u64 sW2[HH * NLP];      // 30720 B, W as packed label-pairs
    __shared__ int sh_slot[TOKPB];
    __shared__ int sh_wsum[WPB];

    int tid  = threadIdx.x;
    int lane = tid & 31;
    int wid  = tid >> 5;

    int tokblk = blockIdx.x * TOKPB;
    int row    = tokblk >> 9;          // / SS
    int r0     = tokblk & (SS - 1);    // row-local index of first token

    int tok0 = tokblk + wid * TPW;
    const float* xb = X + (size_t)tok0 * HH + lane;

    // ---- prologue: prefetch k-chunks 0 and 1 into rotating buffers ----
    float bl[3][TPW], bh[3][TPW];
    #pragma unroll
    for (int c = 0; c < 2; c++)
        #pragma unroll
        for (int t = 0; t < TPW; t++) {
            bl[c][t] = __ldcs(xb + t * HH + 64 * c);
            bh[c][t] = __ldcs(xb + t * HH + 64 * c + 32);
        }

    // ---- W pack into smem (overlaps with in-flight prologue loads) ----
    for (int idx = tid; idx < HH * NLP; idx += 256) {
        int k = idx / NLP;
        int p = idx - k * NLP;
        float lo = W[k * LL + 2 * p];
        float hi = (2 * p + 1 < LL) ? W[k * LL + 2 * p + 1] : 0.f;
        sW2[idx] = pack2(lo, hi);
    }

    // ---- per-row compaction scan (block redundantly scans its whole row) ----
    int2 m2 = ((const int2*)(mask + row * SS))[tid];   // tokens 2*tid, 2*tid+1
    int msum = m2.x + m2.y;
    int v = msum;
    #pragma unroll
    for (int o = 1; o < 32; o <<= 1) {
        int n = __shfl_up_sync(0xffffffffu, v, o);
        if (lane >= o) v += n;
    }
    if (lane == 31) sh_wsum[wid] = v;
    __syncthreads();

    int wpre = 0, total = 0;
    #pragma unroll
    for (int w = 0; w < WPB; w++) {
        int s = sh_wsum[w];
        if (w < wid) wpre += s;
        total += s;
    }
    int run = wpre + v - msum;         // exclusive valid-prefix before token 2*tid

    int mm[2] = {m2.x, m2.y};
    #pragma unroll
    for (int c = 0; c < 2; c++) {
        int sc = 2 * tid + c;
        int code;
        if (mm[c]) { code = run; run++; }
        else       { code = ~(total + sc - run); }   // tail slot, encoded negative
        if (sc >= r0 && sc < r0 + TOKPB) sh_slot[sc - r0] = code;
    }
    __syncthreads();   // covers sW2 + sh_slot

    // ---- main pipelined GEMM ----
    u64 acc[TPW][NLP];
    #pragma unroll
    for (int t = 0; t < TPW; t++)
        #pragma unroll
        for (int p = 0; p < NLP; p++) acc[t][p] = 0ull;

    #pragma unroll
    for (int c = 0; c < NITER; c++) {
        // issue loads for chunk c+2 FIRST (independent of current compute)
        if (c + 2 < NITER) {
            int s = (c + 2) % 3;
            #pragma unroll
            for (int t = 0; t < TPW; t++) {
                bl[s][t] = __ldcs(xb + t * HH + 64 * (c + 2));
                bh[s][t] = __ldcs(xb + t * HH + 64 * (c + 2) + 32);
            }
        }

        // W pairs for this lane's two k-values (conflict-free LDS.64)
        const u64* wl = sW2 + (64 * c + lane) * NLP;
        const u64* wh = wl + 32 * NLP;
        u64 wlr[NLP], whr[NLP];
        #pragma unroll
        for (int p = 0; p < NLP; p++) { wlr[p] = wl[p]; whr[p] = wh[p]; }

        int s = c % 3;
        #pragma unroll
        for (int t = 0; t < TPW; t++) {
            u64 xl = dup2(bl[s][t]);
            u64 xh = dup2(bh[s][t]);
            #pragma unroll
            for (int p = 0; p < NLP; p++) {
                ffma2(acc[t][p], xl, wlr[p]);
                ffma2(acc[t][p], xh, whr[p]);
            }
        }
    }

    // ---- fold pairs to scalars, then butterfly over 20 values ----
    float r[TPW][2 * NLP];
    #pragma unroll
    for (int t = 0; t < TPW; t++)
        #pragma unroll
        for (int p = 0; p < NLP; p++)
            unpack2(acc[t][p], r[t][2 * p], r[t][2 * p + 1]);

    #pragma unroll
    for (int t = 0; t < TPW; t++)
        #pragma unroll
        for (int j = 0; j < LL; j++)      // skip the pad column (j=9)
            #pragma unroll
            for (int o = 16; o > 0; o >>= 1)
                r[t][j] += __shfl_xor_sync(0xffffffffu, r[t][j], o);

    // ---- bias + bias-softmax precompute (cheap, per thread) ----
    float bb[LL], be[LL];
    #pragma unroll
    for (int j = 0; j < LL; j++) bb[j] = bias[j];
    float bmx = bb[0];
    #pragma unroll
    for (int j = 1; j < LL; j++) bmx = fmaxf(bmx, bb[j]);
    float bsum = 0.f;
    #pragma unroll
    for (int j = 0; j < LL; j++) { be[j] = expf(bb[j] - bmx); bsum += be[j]; }
    float binv = 1.f / bsum;

    // ---- finalize: lanes 0..3 each own one token (static indexing) ----
    #pragma unroll
    for (int t = 0; t < TPW; t++) {
        if (lane == t) {
            int code = sh_slot[wid * TPW + t];
            if (code >= 0) {
                float v2[LL];
                float mx = -1e30f;
                #pragma unroll
                for (int j = 0; j < LL; j++) {
                    v2[j] = r[t][j] + bb[j];
                    mx = fmaxf(mx, v2[j]);
                }
                float ssum = 0.f;
                #pragma unroll
                for (int j = 0; j < LL; j++) { v2[j] = expf(v2[j] - mx); ssum += v2[j]; }
                float inv = 1.f / ssum;
                float* o = out + ((size_t)row * SS + code) * LL;
                #pragma unroll
                for (int j = 0; j < LL; j++) o[j] = v2[j] * inv;
            } else {
                int islot = ~code;
                float* o = out + ((size_t)row * SS + islot) * LL;
                #pragma unroll
                for (int j = 0; j < LL; j++) o[j] = be[j] * binv;
            }
        }
    }
}

// ---------------------------------------------------------------------------
// Launch. Inputs (metadata order): sequence_output f32[64*512*768],
// valid_mask i32[64*512], W f32[768*9], b f32[9]. Output f32[64*512*9].
// ---------------------------------------------------------------------------
extern "C" void kernel_launch(void* const* d_in, const int* in_sizes, int n_in,
                              void* d_out, int out_size) {
    const float* X    = (const float*)d_in[0];
    const int*   mask = (const int*)d_in[1];
    const float* W    = (const float*)d_in[2];
    const float* bias = (const float*)d_in[3];
    float* out = (float*)d_out;

    bertner_kernel<<<NTOK / TOKPB, 256>>>(X, mask, W, bias, out);
}

// round 10
// speedup vs baseline: 1.5261x; 1.0647x over previous
#include <cuda_runtime.h>
#include <math.h>

#define BB 64
#define SS 512
#define HH 768
#define LL 9
#define NTOK (BB*SS)
#define TPW 8              // tokens per warp (R2-proven geometry)
#define WPB 4              // warps per block (128 threads)
#define TOKPB (TPW*WPB)    // 32 tokens per block

typedef unsigned long long u64;

__device__ __forceinline__ u64 pack2(float lo, float hi) {
    u64 r; asm("mov.b64 %0, {%1, %2};" : "=l"(r) : "f"(lo), "f"(hi)); return r;
}
__device__ __forceinline__ void unpack2(u64 v, float &lo, float &hi) {
    asm("mov.b64 {%0, %1}, %2;" : "=f"(lo), "=f"(hi) : "l"(v));
}
__device__ __forceinline__ void ffma2(u64 &d, u64 a, u64 b) {
    asm("fma.rn.f32x2 %0, %1, %2, %0;" : "+l"(d) : "l"(a), "l"(b));
}
__device__ __forceinline__ u64 fadd2(u64 a, u64 b) {
    u64 r; asm("add.rn.f32x2 %0, %1, %2;" : "=l"(r) : "l"(a), "l"(b)); return r;
}

// ---------------------------------------------------------------------------
// R2 skeleton (proven fastest) with two targeted changes:
//   - 12 outer iters, each hoisting a 16-deep LDG batch (2 k-steps x 8 tok)
//     before computing both k-steps: 2KB in flight per warp at batch issue.
//   - W stored in smem as PRE-DUPLICATED (w,w) u64 pairs: the hot loop's
//     9 dup-pack ALU movs per k-step vanish; LDS.64 at 18-bank stride is
//     conflict-free across both 16-lane phases.
// Everything else (scan, token-pair f32x2 accs, packed butterfly, softmax
// scatter bijection) identical to the 35.3us kernel.
// ---------------------------------------------------------------------------
__global__ __launch_bounds__(128, 4) void bertner_kernel(
    const float* __restrict__ X, const int* __restrict__ mask,
    const float* __restrict__ W, const float* __restrict__ bias,
    float* __restrict__ out) {

    extern __shared__ u64 sWd[];           // [HH][LL] dup pairs, 55296 B
    __shared__ int sh_slot[TOKPB];
    __shared__ int sh_wsum[WPB];

    int tid  = threadIdx.x;
    int lane = tid & 31;
    int wid  = tid >> 5;

    // ---- W pre-dup fill: sWd[k*9+j] = (W[k][j], W[k][j]) ----
    for (int idx = tid; idx < HH * LL; idx += 128) {
        float w = W[idx];
        sWd[idx] = pack2(w, w);
    }

    // ---- per-row compaction scan (identical to R2) ----
    int tokblk = blockIdx.x * TOKPB;
    int row    = tokblk >> 9;          // / SS
    int r0     = tokblk & (SS - 1);

    int4 m4 = ((const int4*)(mask + row * SS))[tid];   // tokens 4*tid..4*tid+3
    int msum = m4.x + m4.y + m4.z + m4.w;
    int v = msum;
    #pragma unroll
    for (int o = 1; o < 32; o <<= 1) {
        int n = __shfl_up_sync(0xffffffffu, v, o);
        if (lane >= o) v += n;
    }
    if (lane == 31) sh_wsum[wid] = v;
    __syncthreads();

    int wpre = 0;
    #pragma unroll
    for (int w = 0; w < WPB; w++) if (w < wid) wpre += sh_wsum[w];
    int total = sh_wsum[0] + sh_wsum[1] + sh_wsum[2] + sh_wsum[3];
    int run = wpre + v - msum;

    int mm[4] = {m4.x, m4.y, m4.z, m4.w};
    #pragma unroll
    for (int c = 0; c < 4; c++) {
        int sc = 4 * tid + c;
        int code;
        if (mm[c]) { code = run; run++; }
        else       { code = ~(total + sc - run); }
        if (sc >= r0 && sc < r0 + TOKPB) sh_slot[sc - r0] = code;
    }
    __syncthreads();   // covers sWd + sh_slot

    // ---- main GEMM: warp handles 8 tokens; lane owns k = lane + 32*i ----
    int tok0 = tokblk + wid * TPW;
    const float* xb = X + (size_t)tok0 * HH + lane;

    u64 acc[TPW/2][LL];
    #pragma unroll
    for (int p = 0; p < TPW/2; p++)
        #pragma unroll
        for (int j = 0; j < LL; j++) acc[p][j] = 0ull;

    for (int i = 0; i < HH / 64; i++) {       // 12 outer iterations
        int k0 = i * 64;

        // hoisted 16-deep load batch: 2 k-steps x 8 tokens
        float xv[2][TPW];
        #pragma unroll
        for (int u = 0; u < 2; u++)
            #pragma unroll
            for (int t = 0; t < TPW; t++)
                xv[u][t] = xb[t * HH + k0 + u * 32];

        #pragma unroll
        for (int u = 0; u < 2; u++) {
            int k = k0 + u * 32 + lane;
            const u64* wd = sWd + k * LL;
            u64 w[LL];
            #pragma unroll
            for (int j = 0; j < LL; j++) w[j] = wd[j];   // LDS.64, conflict-free

            u64 xp[TPW/2];
            #pragma unroll
            for (int p = 0; p < TPW/2; p++) xp[p] = pack2(xv[u][2*p], xv[u][2*p+1]);

            #pragma unroll
            for (int j = 0; j < LL; j++)
                #pragma unroll
                for (int p = 0; p < TPW/2; p++) ffma2(acc[p][j], xp[p], w[j]);
        }
    }

    // ---- packed butterfly reduction: every lane ends with full sums ----
    #pragma unroll
    for (int p = 0; p < TPW/2; p++)
        #pragma unroll
        for (int j = 0; j < LL; j++)
            #pragma unroll
            for (int o = 16; o > 0; o >>= 1) {
                u64 other = __shfl_xor_sync(0xffffffffu, acc[p][j], o);
                acc[p][j] = fadd2(acc[p][j], other);
            }

    // ---- bias + bias-softmax precompute ----
    float bb[LL], be[LL];
    #pragma unroll
    for (int j = 0; j < LL; j++) bb[j] = bias[j];
    float bmx = bb[0];
    #pragma unroll
    for (int j = 1; j < LL; j++) bmx = fmaxf(bmx, bb[j]);
    float bsum = 0.f;
    #pragma unroll
    for (int j = 0; j < LL; j++) { be[j] = expf(bb[j] - bmx); bsum += be[j]; }
    float binv = 1.f / bsum;

    // ---- finalize: lanes 0..7 each own one token (static acc indexing) ----
    #pragma unroll
    for (int t = 0; t < TPW; t++) {
        if (lane == t) {
            int code = sh_slot[wid * TPW + t];
            if (code >= 0) {
                float v2[LL];
                float mx = -1e30f;
                #pragma unroll
                for (int j = 0; j < LL; j++) {
                    float lo, hi;
                    unpack2(acc[t >> 1][j], lo, hi);
                    v2[j] = ((t & 1) ? hi : lo) + bb[j];
                    mx = fmaxf(mx, v2[j]);
                }
                float ssum = 0.f;
                #pragma unroll
                for (int j = 0; j < LL; j++) { v2[j] = expf(v2[j] - mx); ssum += v2[j]; }
                float inv = 1.f / ssum;
                float* o = out + ((size_t)row * SS + code) * LL;
                #pragma unroll
                for (int j = 0; j < LL; j++) o[j] = v2[j] * inv;
            } else {
                int islot = ~code;
                float* o = out + ((size_t)row * SS + islot) * LL;
                #pragma unroll
                for (int j = 0; j < LL; j++) o[j] = be[j] * binv;
            }
        }
    }
}

// ---------------------------------------------------------------------------
// Launch. Inputs (metadata order): sequence_output f32[64*512*768],
// valid_mask i32[64*512], W f32[768*9], b f32[9]. Output f32[64*512*9].
// ---------------------------------------------------------------------------
extern "C" void kernel_launch(void* const* d_in, const int* in_sizes, int n_in,
                              void* d_out, int out_size) {
    const float* X    = (const float*)d_in[0];
    const int*   mask = (const int*)d_in[1];
    const float* W    = (const float*)d_in[2];
    const float* bias = (const float*)d_in[3];
    float* out = (float*)d_out;

    int smem = HH * LL * (int)sizeof(u64);   // 55296 B
    cudaFuncSetAttribute(bertner_kernel,
                         cudaFuncAttributeMaxDynamicSharedMemorySize, smem);
    bertner_kernel<<<NTOK / TOKPB, 128, smem>>>(X, mask, W, bias, out);
}